// round 1
// baseline (speedup 1.0000x reference)
#include <cuda_runtime.h>

#define T_STEPS 100
#define BB      512
#define NIN     784
#define HH      1024
#define OO      10

#define BETA    0.95f
#define DECAYC  0.05f   // DT / STDP_DECAY
#define A_PLUS  0.01f
#define A_MINUS 0.01f

// Precomputed column-sums of W1 rows: colsum[h] = sum_k W1[h,k]
__device__ __align__(16) float g_colsum[HH];

// ---------------------------------------------------------------------------
// colsum kernel: one warp per row h. Deterministic (fixed stride + shfl tree).
// ---------------------------------------------------------------------------
__global__ void colsum_kernel(const float* __restrict__ W1) {
    int warp_in_block = threadIdx.x >> 5;
    int lane = threadIdx.x & 31;
    int h = blockIdx.x * (blockDim.x >> 5) + warp_in_block;
    if (h >= HH) return;
    float s = 0.f;
    for (int k = lane; k < NIN; k += 32) s += W1[(size_t)h * NIN + k];
#pragma unroll
    for (int off = 16; off; off >>= 1) s += __shfl_xor_sync(0xffffffffu, s, off);
    if (lane == 0) g_colsum[h] = s;
}

// ---------------------------------------------------------------------------
// Main SNN kernel: one block per batch element, whole T loop inside.
// 256 threads. Thread t owns 4 consecutive neurons (float4 everywhere).
// All carry state in shared / registers -> only traffic is x reads + outputs.
// ---------------------------------------------------------------------------
__global__ void __launch_bounds__(256)
snn_kernel(const float* __restrict__ x,
           const float* __restrict__ W1,
           const float* __restrict__ W2,
           const float* __restrict__ thr1,
           const float* __restrict__ thr2,
           float* __restrict__ out)
{
    __shared__ float4 s_mem0[NIN / 4], s_pre0[NIN / 4], s_post0[NIN / 4];
    __shared__ float4 s_mem1[HH / 4], s_pre1[HH / 4], s_post1[HH / 4];
    __shared__ unsigned s_zmask[32];
    __shared__ unsigned short s_zlist[NIN];
    __shared__ int s_nz;
    __shared__ float s_red[8][OO];

    const int b    = blockIdx.x;
    const int tid  = threadIdx.x;
    const int warp = tid >> 5;
    const int lane = tid & 31;
    const bool act0 = (tid < NIN / 4);   // layer-0 ownership: 196 threads

    const float4 zero4 = make_float4(0.f, 0.f, 0.f, 0.f);

    // ---- init carries ----
    if (act0) { s_mem0[tid] = zero4; s_pre0[tid] = zero4; s_post0[tid] = zero4; }
    s_mem1[tid] = zero4; s_pre1[tid] = zero4; s_post1[tid] = zero4;

    // per-thread constants for layer 1 (h = 4*tid + j)
    const float4 cs4  = ((const float4*)g_colsum)[tid];
    const float4 th14 = ((const float4*)thr1)[tid];

    // layer-2 state lives in registers of threads 0..9
    float mem2 = 0.f, pre2 = 0.f, post2 = 0.f, th2 = 0.f;
    if (tid < OO) th2 = thr2[tid];

    __syncthreads();

    // ---- output tensor bases (pytree order) ----
    const size_t S0 = (size_t)T_STEPS * BB * NIN;
    const size_t S1 = (size_t)T_STEPS * BB * HH;
    const size_t S2 = (size_t)T_STEPS * BB * OO;
    float* o_spk0  = out;
    float* o_pre0  = out + S0;
    float* o_post0 = out + 2 * S0;
    float* o_spk1  = out + 3 * S0;
    float* o_pre1  = out + 3 * S0 + S1;
    float* o_post1 = out + 3 * S0 + 2 * S1;
    float* o_spk2  = out + 3 * S0 + 3 * S1;
    float* o_mem2  = o_spk2 + S2;
    float* o_pre2  = o_spk2 + 2 * S2;
    float* o_post2 = o_spk2 + 3 * S2;

    const float4* W24 = (const float4*)W2;   // W2[o*HH + 4*tid+j] = W24[o*256 + tid]

    for (int t = 0; t < T_STEPS; ++t) {
        // ================= Layer 0 (thr = 0, subtract-reset => no-op reset) ======
        const size_t base0 = ((size_t)t * BB + b) * NIN;
        float s0[4] = {0.f, 0.f, 0.f, 0.f};
        if (act0) {
            const float4 xt = ((const float4*)(x + base0))[tid];
            float4 m = s_mem0[tid], pr = s_pre0[tid], po = s_post0[tid];
            float xin[4] = {xt.x, xt.y, xt.z, xt.w};
            float mm[4] = {m.x, m.y, m.z, m.w};
            float pp[4] = {pr.x, pr.y, pr.z, pr.w};
            float qq[4] = {po.x, po.y, po.z, po.w};
#pragma unroll
            for (int j = 0; j < 4; ++j) {
                float mn = BETA * mm[j] + xin[j];      // thr=0 -> reset subtracts 0
                mm[j] = mn;
                float spk = (mn > 0.f) ? 1.f : 0.f;
                s0[j] = spk;
                pp[j] = pp[j] - DECAYC * pp[j] + A_PLUS * spk;
                qq[j] = qq[j] - DECAYC * qq[j] - A_MINUS * spk;
            }
            s_mem0[tid]  = make_float4(mm[0], mm[1], mm[2], mm[3]);
            float4 prn = make_float4(pp[0], pp[1], pp[2], pp[3]);
            float4 pon = make_float4(qq[0], qq[1], qq[2], qq[3]);
            s_pre0[tid]  = prn;
            s_post0[tid] = pon;
            ((float4*)(o_spk0  + base0))[tid] = make_float4(s0[0], s0[1], s0[2], s0[3]);
            ((float4*)(o_pre0  + base0))[tid] = prn;
            ((float4*)(o_post0 + base0))[tid] = pon;
        }
        // zero-spike bitmask (deterministic order): word = j*8 + warp
#pragma unroll
        for (int j = 0; j < 4; ++j) {
            unsigned m = __ballot_sync(0xffffffffu, act0 && (s0[j] == 0.f));
            if (lane == 0) s_zmask[j * 8 + warp] = m;
        }
        __syncthreads();

        // ========== expand bitmask -> ordered index list (warp 0 only) ==========
        if (warp == 0) {
            unsigned w = s_zmask[lane];
            int cnt = __popc(w);
            int incl = cnt;
#pragma unroll
            for (int off = 1; off < 32; off <<= 1) {
                int v = __shfl_up_sync(0xffffffffu, incl, off);
                if (lane >= off) incl += v;
            }
            int pos = incl - cnt;
            int j = lane >> 3, wp = lane & 7;
            while (w) {
                int bit = __ffs(w) - 1;
                w &= w - 1;
                s_zlist[pos++] = (unsigned short)(4 * (wp * 32 + bit) + j);
            }
            if (lane == 31) s_nz = incl;
        }
        __syncthreads();
        const int nz = s_nz;

        // ================= Layer 1 (thr1, zero-reset) ===========================
        const size_t base1 = ((size_t)t * BB + b) * HH;
        float cur[4] = {cs4.x, cs4.y, cs4.z, cs4.w};
        for (int zj = 0; zj < nz; ++zj) {
            int kz = s_zlist[zj];
#pragma unroll
            for (int j = 0; j < 4; ++j)
                cur[j] -= W1[(size_t)(4 * tid + j) * NIN + kz];
        }
        float spk1[4];
        {
            float4 m = s_mem1[tid], pr = s_pre1[tid], po = s_post1[tid];
            float mm[4] = {m.x, m.y, m.z, m.w};
            float pp[4] = {pr.x, pr.y, pr.z, pr.w};
            float qq[4] = {po.x, po.y, po.z, po.w};
            float th[4] = {th14.x, th14.y, th14.z, th14.w};
#pragma unroll
            for (int j = 0; j < 4; ++j) {
                float c = fmaxf(cur[j], 0.f);
                float reset = (mm[j] > th[j]) ? 1.f : 0.f;
                float mn = (BETA * mm[j] + c) * (1.f - reset);
                mm[j] = mn;
                float spk = ((mn - th[j]) > 0.f) ? 1.f : 0.f;
                spk1[j] = spk;
                pp[j] = pp[j] - DECAYC * pp[j] + A_PLUS * spk;
                qq[j] = qq[j] - DECAYC * qq[j] - A_MINUS * spk;
            }
            s_mem1[tid] = make_float4(mm[0], mm[1], mm[2], mm[3]);
            float4 prn = make_float4(pp[0], pp[1], pp[2], pp[3]);
            float4 pon = make_float4(qq[0], qq[1], qq[2], qq[3]);
            s_pre1[tid]  = prn;
            s_post1[tid] = pon;
            ((float4*)(o_spk1  + base1))[tid] = make_float4(spk1[0], spk1[1], spk1[2], spk1[3]);
            ((float4*)(o_pre1  + base1))[tid] = prn;
            ((float4*)(o_post1 + base1))[tid] = pon;
        }

        // ================= Layer 2 dot: cur2[o] = sum_h spk1[h] * W2[o,h] =======
        float acc[OO];
#pragma unroll
        for (int o = 0; o < OO; ++o) acc[o] = 0.f;
#pragma unroll
        for (int o = 0; o < OO; ++o) {
            float4 w = W24[o * (HH / 4) + tid];
            acc[o] = spk1[0] * w.x + spk1[1] * w.y + spk1[2] * w.z + spk1[3] * w.w;
        }
#pragma unroll
        for (int o = 0; o < OO; ++o) {
#pragma unroll
            for (int off = 16; off; off >>= 1)
                acc[o] += __shfl_xor_sync(0xffffffffu, acc[o], off);
        }
        if (lane == 0) {
#pragma unroll
            for (int o = 0; o < OO; ++o) s_red[warp][o] = acc[o];
        }
        __syncthreads();

        if (tid < OO) {
            float c2 = 0.f;
#pragma unroll
            for (int w = 0; w < 8; ++w) c2 += s_red[w][tid];
            c2 = fmaxf(c2, 0.f);
            float reset = (mem2 > th2) ? 1.f : 0.f;
            mem2 = (BETA * mem2 + c2) * (1.f - reset);
            float spk = ((mem2 - th2) > 0.f) ? 1.f : 0.f;
            pre2  = pre2  - DECAYC * pre2  + A_PLUS  * spk;
            post2 = post2 - DECAYC * post2 - A_MINUS * spk;
            const size_t base2 = ((size_t)t * BB + b) * OO + tid;
            o_spk2[base2]  = spk;
            o_mem2[base2]  = mem2;
            o_pre2[base2]  = pre2;
            o_post2[base2] = post2;
        }
        __syncthreads();   // protect s_red / s_zmask / s_zlist for next iteration
    }
}

// ---------------------------------------------------------------------------
extern "C" void kernel_launch(void* const* d_in, const int* in_sizes, int n_in,
                              void* d_out, int out_size) {
    const float* x    = (const float*)d_in[0];
    const float* W1   = (const float*)d_in[1];
    const float* W2   = (const float*)d_in[2];
    const float* thr1 = (const float*)d_in[3];
    const float* thr2 = (const float*)d_in[4];
    float* out = (float*)d_out;
    (void)in_sizes; (void)n_in; (void)out_size;

    colsum_kernel<<<HH / 4, 128>>>(W1);
    snn_kernel<<<BB, 256>>>(x, W1, W2, thr1, thr2, out);
}